// round 14
// baseline (speedup 1.0000x reference)
#include <cuda_runtime.h>
#include <cuda_fp16.h>
#include <math.h>
#include <cstdint>

#define NN 50000
#define NE 800000
#define CH 64
#define SEQL 8
#define KB 192
#define SCB 49
#define PADH 72
#define NTILE ((NN + 127) / 128)

static const size_t SL  = (size_t)NN * CH;
static const size_t SLK = (size_t)NN * KB;

// ---------------- static scratch ----------------
__device__ float  g_deg[NN];
__device__ int    g_cnt[NN];
__device__ int    g_off[NN + 1];
__device__ int    g_cur[NN];
__device__ int    g_pref[SCB];
__device__ int    g_rdy[SCB];
__device__ int    g_cnt_bar;
__device__ int    g_gen_bar;
__device__ int2   g_cw[NE];                      // packed {col, w-bits}
__device__ __half g_Xh [(size_t)SEQL * NN * CH]; // fp16 X, all t
__device__ __half g_Hh [(size_t)NN * CH];        // fp16 H state
__device__ __half g_HRh[(size_t)NN * CH];        // fp16 H*R
__device__ __half g_T1X[(size_t)SEQL * NN * CH]; // T1 per t (X stage)
__device__ __half g_T1H[(size_t)NN * CH];        // T1 (chain, reused)
__device__ float  g_GX [(size_t)SEQL * NN * KB]; // x-gate preactivations
__device__ float  g_Z  [(size_t)NN * CH];
__device__ __half g_BX [192 * KB];               // fp16 transposed weights
__device__ __half g_BZR[128 * KB];
__device__ __half g_BH [64 * KB];
__device__ float  g_bX [192];
__device__ float  g_bZR[128];

// ---------------- helpers ----------------
__device__ __forceinline__ void mma_f16(float* d, const uint32_t* a, const uint32_t* b) {
    asm volatile(
        "mma.sync.aligned.m16n8k16.row.col.f32.f16.f16.f32 "
        "{%0,%1,%2,%3}, {%4,%5,%6,%7}, {%8,%9}, {%0,%1,%2,%3};\n"
        : "+f"(d[0]), "+f"(d[1]), "+f"(d[2]), "+f"(d[3])
        : "r"(a[0]), "r"(a[1]), "r"(a[2]), "r"(a[3]), "r"(b[0]), "r"(b[1]));
}

// software grid barrier (all blocks resident by occupancy-sized grid)
__device__ __forceinline__ void grid_bar(int nb) {
    __syncthreads();
    if (threadIdx.x == 0) {
        __threadfence();
        int gen = atomicAdd(&g_gen_bar, 0);
        if (atomicAdd(&g_cnt_bar, 1) == nb - 1) {
            g_cnt_bar = 0;
            __threadfence();
            atomicExch(&g_gen_bar, gen + 1);
        } else {
            while (atomicAdd(&g_gen_bar, 0) == gen) __nanosleep(64);
        }
        __threadfence();
    }
    __syncthreads();
}

// ---------------- setup ----------------
__global__ void k_init() {
    int i = blockIdx.x * blockDim.x + threadIdx.x;
    if (i < NN) { g_deg[i] = 0.f; g_cnt[i] = 0; g_cur[i] = 0; }
    if (i < SCB) g_rdy[i] = 0;
    if (i == 0) { g_cnt_bar = 0; g_gen_bar = 0; }
}
__global__ void k_edgepre(const int* __restrict__ ei, const float* __restrict__ ew) {
    int e = blockIdx.x * blockDim.x + threadIdx.x;
    if (e < NE) {
        int r = ei[e], c = ei[NE + e];
        if (r != c) atomicAdd(&g_deg[r], ew[e]);
        atomicAdd(&g_cnt[r], 1);
    }
}
// chained-prefix scan: 49 blocks, block b waits on b-1
__global__ void k_scanLB() {
    __shared__ int sh[1024];
    __shared__ int s_pre;
    int b = blockIdx.x, t = threadIdx.x, idx = b * 1024 + t;
    int v = (idx < NN) ? g_cnt[idx] : 0;
    sh[t] = v; __syncthreads();
    for (int d = 1; d < 1024; d <<= 1) {
        int u = (t >= d) ? sh[t - d] : 0;
        __syncthreads(); sh[t] += u; __syncthreads();
    }
    if (t == 0) {
        int total = sh[1023];
        int pre = 0;
        if (b > 0) {
            while (atomicAdd(&g_rdy[b - 1], 0) == 0) __nanosleep(32);
            __threadfence();
            pre = g_pref[b - 1];
        }
        g_pref[b] = pre + total;
        __threadfence();
        atomicExch(&g_rdy[b], 1);
        s_pre = pre;
    }
    __syncthreads();
    if (idx < NN) g_off[idx] = s_pre + sh[t] - v;
    if (b == SCB - 1 && t == 1023) g_off[NN] = NE;
}
__global__ void k_scatter(const int* __restrict__ ei, const float* __restrict__ ew) {
    int e = blockIdx.x * blockDim.x + threadIdx.x;
    if (e < NE) {
        int r = ei[e], c = ei[NE + e];
        float w = (r == c) ? 0.f : ew[e];
        float dr = g_deg[r], dc = g_deg[c];
        float wn = -w * (dr > 0.f ? rsqrtf(dr) : 0.f) * (dc > 0.f ? rsqrtf(dc) : 0.f);
        int pos = g_off[r] + atomicAdd(&g_cur[r], 1);
        g_cw[pos] = make_int2(c, __float_as_int(wn));
    }
}
// fused: transposed fp16 weights + bias concat + X fp32->fp16
__global__ void k_prep(const float* __restrict__ Wxz, const float* __restrict__ Wxr,
                       const float* __restrict__ Wxh, const float* __restrict__ Whz,
                       const float* __restrict__ Whr, const float* __restrict__ Whh,
                       const float* __restrict__ bxz, const float* __restrict__ bxr,
                       const float* __restrict__ bxh, const float* __restrict__ bhz,
                       const float* __restrict__ bhr, const float* __restrict__ X, int n4) {
    int i = blockIdx.x * blockDim.x + threadIdx.x;
    if (i < 192 * KB) {
        int n = i / KB, k = i % KB, kc = k / 64, ci = k & 63, gate = n / 64, c = n & 63;
        const float* W = gate == 0 ? Wxz : (gate == 1 ? Wxr : Wxh);
        g_BX[i] = __float2half(W[kc * 4096 + ci * 64 + c]);
    }
    if (i < 128 * KB) {
        int n = i / KB, k = i % KB, kc = k / 64, ci = k & 63, c = n & 63;
        const float* W = n < 64 ? Whz : Whr;
        g_BZR[i] = __float2half(W[kc * 4096 + ci * 64 + c]);
    }
    if (i < 64 * KB) {
        int n = i / KB, k = i % KB, kc = k / 64, ci = k & 63;
        g_BH[i] = __float2half(Whh[kc * 4096 + ci * 64 + (n & 63)]);
    }
    if (i < 192) g_bX[i] = i < 64 ? bxz[i] : (i < 128 ? bxr[i - 64] : bxh[i - 128]);
    if (i < 128) g_bZR[i] = i < 64 ? bhz[i] : bhr[i - 64];
    if (i < n4) {
        float4 v = ((const float4*)X)[i];
        __half2 h0 = __floats2half2_rn(v.x, v.y);
        __half2 h1 = __floats2half2_rn(v.z, v.w);
        ((uint2*)g_Xh)[i] = make_uint2(*(uint32_t*)&h0, *(uint32_t*)&h1);
    }
}

// ---------------- SpMM body: one row, quarter-warp per edge ----------------
__device__ __forceinline__ void spmm_row(const __half* __restrict__ vh, __half* __restrict__ T1,
                                         int row, int sub, int cg) {
    const uint4* v4 = (const uint4*)vh;
    int s = g_off[row], e = g_off[row + 1];
    float acc[8];
#pragma unroll
    for (int k = 0; k < 8; k++) acc[k] = 0.f;
    for (int j = s + sub; j < e; j += 4) {
        int2 cw = g_cw[j];
        float w = __int_as_float(cw.y);
        uint4 u = v4[(size_t)cw.x * 8 + cg];
        const __half2* h = (const __half2*)&u;
#pragma unroll
        for (int k = 0; k < 4; k++) {
            float2 f = __half22float2(h[k]);
            acc[2 * k]     += w * f.x;
            acc[2 * k + 1] += w * f.y;
        }
    }
#pragma unroll
    for (int d = 8; d <= 16; d <<= 1)
#pragma unroll
        for (int k = 0; k < 8; k++)
            acc[k] += __shfl_xor_sync(0xffffffffu, acc[k], d);
    if (sub == 0) {
        uint4 r; __half2* rh = (__half2*)&r;
#pragma unroll
        for (int k = 0; k < 4; k++) rh[k] = __floats2half2_rn(acc[2 * k], acc[2 * k + 1]);
        ((uint4*)T1)[(size_t)row * 8 + cg] = r;
    }
}

// standalone batched X SpMM: T1X[t] = S @ Xh[t]
__global__ void k_spmmX() {
    int warp = (blockIdx.x * blockDim.x + threadIdx.x) >> 5;
    if (warp >= NN) return;
    int lane = threadIdx.x & 31;
    spmm_row(g_Xh + (size_t)blockIdx.y * SL, g_T1X + (size_t)blockIdx.y * SL,
             warp, lane >> 3, lane & 7);
}

// ---------------- fgemm tile body (device) ----------------
// acc = T0@W0 + T1@W1 + T2@W2, T2 = 2*(S@T1) - T0 gathered into smem.
// NWARPS = blockDim.x/32 must be 8 (256 thr) for chain, 12 (384) for X.
template <int NOUT, int EPI, int NTH>
__device__ __forceinline__ void fgemm_tile(
    int rb, const __half* __restrict__ T0, const __half* __restrict__ T1p,
    const __half* __restrict__ B, const float* __restrict__ bias,
    const float* __restrict__ GX, const float* __restrict__ H,
    const float* __restrict__ Z, float* __restrict__ out,
    __half* __restrict__ outh, __half* sm)
{
    const int NW = NTH / 32;
    const int NWN = (NTH == 384) ? 3 : 2;       // N warp groups
    const int NHALF = NOUT / NWN;               // cols per N-group
    const int NT = NHALF / 8;
    __half* As  = sm;
    __half* T2s = As + 128 * PADH;
    __half* Bs  = T2s + 128 * PADH;
    int tid = threadIdx.x, wid = tid >> 5, lane = tid & 31;
    int mw = wid & 3, nw = wid >> 2;
    int g = lane >> 2, tq = lane & 3, sub = lane >> 3, cg = lane & 7;

    // T2 prologue
    for (int row = wid; row < 128; row += NW) {
        int gr = rb + row;
        float acc[8];
#pragma unroll
        for (int k = 0; k < 8; k++) acc[k] = 0.f;
        if (gr < NN) {
            const uint4* v4 = (const uint4*)T1p;
            int s = g_off[gr], e = g_off[gr + 1];
            for (int j = s + sub; j < e; j += 4) {
                int2 cw = g_cw[j];
                float w = __int_as_float(cw.y);
                uint4 u = v4[(size_t)cw.x * 8 + cg];
                const __half2* h = (const __half2*)&u;
#pragma unroll
                for (int k = 0; k < 4; k++) {
                    float2 f = __half22float2(h[k]);
                    acc[2 * k]     += w * f.x;
                    acc[2 * k + 1] += w * f.y;
                }
            }
        }
#pragma unroll
        for (int d = 8; d <= 16; d <<= 1)
#pragma unroll
            for (int k = 0; k < 8; k++)
                acc[k] += __shfl_xor_sync(0xffffffffu, acc[k], d);
        if (sub == 0) {
            uint4 t0u = make_uint4(0u, 0u, 0u, 0u);
            if (gr < NN) t0u = *(const uint4*)(T0 + (size_t)gr * CH + cg * 8);
            const __half2* th = (const __half2*)&t0u;
            uint4 r; __half2* rh = (__half2*)&r;
#pragma unroll
            for (int k = 0; k < 4; k++) {
                float2 tf = __half22float2(th[k]);
                rh[k] = __floats2half2_rn(2.f * acc[2 * k] - tf.x,
                                          2.f * acc[2 * k + 1] - tf.y);
            }
            *(uint4*)&T2s[row * PADH + cg * 8] = r;
        }
    }
    __syncthreads();

    float acc[2][NT][4];
#pragma unroll
    for (int mt = 0; mt < 2; mt++)
#pragma unroll
        for (int nt = 0; nt < NT; nt++)
#pragma unroll
            for (int q = 0; q < 4; q++) acc[mt][nt][q] = 0.f;

    for (int kc = 0; kc < 3; kc++) {
        if (kc < 2) {
            const __half* Asrc = (kc == 0) ? T0 : T1p;
#pragma unroll
            for (int idx = tid; idx < 1024; idx += NTH) {
                int row = idx >> 3, q = idx & 7;
                uint4 v = make_uint4(0u, 0u, 0u, 0u);
                int gr = rb + row;
                if (gr < NN) v = *(const uint4*)(Asrc + (size_t)gr * CH + q * 8);
                *(uint4*)&As[row * PADH + q * 8] = v;
            }
        }
#pragma unroll
        for (int idx = tid; idx < NOUT * 8; idx += NTH) {
            int row = idx >> 3, q = idx & 7;
            uint4 v = *(const uint4*)(B + (size_t)row * KB + kc * 64 + q * 8);
            *(uint4*)&Bs[row * PADH + q * 8] = v;
        }
        __syncthreads();
        const __half* At = (kc == 2) ? T2s : As;
#pragma unroll
        for (int kk = 0; kk < 4; kk++) {
            int kb = kk * 16 + tq * 2;
            uint32_t a[2][4];
#pragma unroll
            for (int mt = 0; mt < 2; mt++) {
                int r = mw * 32 + mt * 16 + g;
                a[mt][0] = *(const uint32_t*)&At[r * PADH + kb];
                a[mt][1] = *(const uint32_t*)&At[(r + 8) * PADH + kb];
                a[mt][2] = *(const uint32_t*)&At[r * PADH + kb + 8];
                a[mt][3] = *(const uint32_t*)&At[(r + 8) * PADH + kb + 8];
            }
            uint32_t b[NT][2];
#pragma unroll
            for (int nt = 0; nt < NT; nt++) {
                int n = nw * NHALF + nt * 8 + g;
                b[nt][0] = *(const uint32_t*)&Bs[n * PADH + kb];
                b[nt][1] = *(const uint32_t*)&Bs[n * PADH + kb + 8];
            }
#pragma unroll
            for (int mt = 0; mt < 2; mt++)
#pragma unroll
                for (int nt = 0; nt < NT; nt++)
                    mma_f16(acc[mt][nt], a[mt], b[nt]);
        }
        __syncthreads();
    }

    // epilogue
#pragma unroll
    for (int mt = 0; mt < 2; mt++) {
#pragma unroll
        for (int nt = 0; nt < NT; nt++) {
            int c = nw * NHALF + nt * 8 + tq * 2;
            float bx = bias[c], by = bias[c + 1];
#pragma unroll
            for (int hh = 0; hh < 2; hh++) {
                int r = rb + mw * 32 + mt * 16 + g + hh * 8;
                if (r >= NN) continue;
                float vx = acc[mt][nt][hh * 2] + bx;
                float vy = acc[mt][nt][hh * 2 + 1] + by;
                if (EPI == 0) {
                    *(float2*)(out + (size_t)r * KB + c) = make_float2(vx, vy);
                } else if (EPI == 1) {
                    float2 gx = *(const float2*)(GX + (size_t)r * KB + c);
                    float sx = 1.f / (1.f + expf(-(vx + gx.x)));
                    float sy = 1.f / (1.f + expf(-(vy + gx.y)));
                    if (c < 64) {
                        *(float2*)(out + (size_t)r * CH + c) = make_float2(sx, sy);
                    } else {
                        float2 h = *(const float2*)(H + (size_t)r * CH + (c - 64));
                        *(__half2*)(outh + (size_t)r * CH + (c - 64)) =
                            __floats2half2_rn(h.x * sx, h.y * sy);
                    }
                } else {
                    float2 gx = *(const float2*)(GX + (size_t)r * KB + 128 + c);
                    float2 h  = *(const float2*)(H + (size_t)r * CH + c);
                    float2 z2 = *(const float2*)(Z + (size_t)r * CH + c);
                    float tx = tanhf(vx + gx.x), ty = tanhf(vy + gx.y);
                    float ox = z2.x * h.x + (1.f - z2.x) * tx;
                    float oy = z2.y * h.y + (1.f - z2.y) * ty;
                    *(float2*)(out + (size_t)r * CH + c) = make_float2(ox, oy);
                    *(__half2*)(outh + (size_t)r * CH + c) = __floats2half2_rn(ox, oy);
                }
            }
        }
    }
}

// ---------------- standalone batched X GEMM (EPI 0, NOUT=192, 384 thr) ----
__global__ void __launch_bounds__(384) k_fgemmX(const float* __restrict__ bias) {
    extern __shared__ __half sm[];
    size_t t = blockIdx.y;
    fgemm_tile<192, 0, 384>(blockIdx.x * 128, g_Xh + t * SL, g_T1X + t * SL,
                            g_BX, bias, nullptr, nullptr, nullptr,
                            g_GX + t * SLK, nullptr, sm);
}

// ---------------- persistent chain kernel: t = 1..7, 4 phases each --------
__global__ void __launch_bounds__(256, 2) k_chain(
    float* __restrict__ out, const float* __restrict__ bZR,
    const float* __restrict__ bhh, int nb)
{
    extern __shared__ __half sm[];
    int tid = threadIdx.x, lane = tid & 31;
    int gwarp = (blockIdx.x * 256 + tid) >> 5;
    int totw = nb * 8;
    int sub = lane >> 3, cg = lane & 7;

    for (int t = 1; t < SEQL; t++) {
        const float* Hp  = out + (size_t)(t - 1) * SL;
        const float* GXt = g_GX + (size_t)t * SLK;
        float* Ot = out + (size_t)t * SL;

        // phase 1: T1 = S @ Hh
        for (int row = gwarp; row < NN; row += totw)
            spmm_row(g_Hh, g_T1H, row, sub, cg);
        grid_bar(nb);
        // phase 2: Z / HR gemm
        for (int tile = blockIdx.x; tile < NTILE; tile += nb)
            fgemm_tile<128, 1, 256>(tile * 128, g_Hh, g_T1H, g_BZR, bZR,
                                    GXt, Hp, nullptr, g_Z, g_HRh, sm);
        grid_bar(nb);
        // phase 3: T1 = S @ HRh
        for (int row = gwarp; row < NN; row += totw)
            spmm_row(g_HRh, g_T1H, row, sub, cg);
        grid_bar(nb);
        // phase 4: candidate + GRU combine
        for (int tile = blockIdx.x; tile < NTILE; tile += nb)
            fgemm_tile<64, 2, 256>(tile * 128, g_HRh, g_T1H, g_BH, bhh,
                                   GXt, Hp, g_Z, Ot, g_Hh, sm);
        grid_bar(nb);
    }
}

// t = 0: H0 = 0 => Hn = (1 - sigmoid(GXz + b_hz)) * tanh(GXh + b_hh)
__global__ void k_t0(const float* __restrict__ bhz, const float* __restrict__ bhh,
                     float* __restrict__ out) {
    int i = blockIdx.x * blockDim.x + threadIdx.x;
    if (i >= NN * CH) return;
    int r = i >> 6, c = i & 63;
    float z  = 1.f / (1.f + expf(-(g_GX[(size_t)r * KB + c] + bhz[c])));
    float ht = tanhf(g_GX[(size_t)r * KB + 128 + c] + bhh[c]);
    float res = (1.f - z) * ht;
    out[i] = res;
    g_Hh[i] = __float2half(res);
}

__global__ void k_copy(const float* __restrict__ src, float* __restrict__ dst, int n) {
    int i = blockIdx.x * blockDim.x + threadIdx.x;
    if (i < n) dst[i] = src[i];
}

// ---------------- host side ----------------
extern "C" void kernel_launch(void* const* d_in, const int* in_sizes, int n_in,
                              void* d_out, int out_size) {
    const float* X    = (const float*)d_in[0];
    const int*   ei   = (const int*)  d_in[1];
    const float* ew   = (const float*)d_in[2];
    const float* W_xz = (const float*)d_in[3];
    const float* b_xz = (const float*)d_in[4];
    const float* W_hz = (const float*)d_in[5];
    const float* b_hz = (const float*)d_in[6];
    const float* W_xr = (const float*)d_in[7];
    const float* b_xr = (const float*)d_in[8];
    const float* W_hr = (const float*)d_in[9];
    const float* b_hr = (const float*)d_in[10];
    const float* W_xh = (const float*)d_in[11];
    const float* b_xh = (const float*)d_in[12];
    const float* W_hh = (const float*)d_in[13];
    const float* b_hh = (const float*)d_in[14];
    float* out = (float*)d_out;

    float *pbX, *pbZR;
    cudaGetSymbolAddress((void**)&pbX,  g_bX);
    cudaGetSymbolAddress((void**)&pbZR, g_bZR);

    const int NB_NODE = (NN + 255) / 256;
    const int NB_EDGE = (NE + 255) / 256;
    const int NB_SPMM = (NN * 32 + 255) / 256;
    const int NX4 = SEQL * NN * CH / 4;
    const int SMX    = (128 * 2 + 192) * PADH * (int)sizeof(__half);  // 64512
    const int SMCH   = (128 * 2 + 128) * PADH * (int)sizeof(__half);  // 55296

    cudaFuncSetAttribute(k_fgemmX, cudaFuncAttributeMaxDynamicSharedMemorySize, SMX);
    cudaFuncSetAttribute(k_chain,  cudaFuncAttributeMaxDynamicSharedMemorySize, SMCH);

    // persistent-grid sizing with residency guarantee
    int dev = 0, nsm = 148, occ = 0;
    cudaGetDevice(&dev);
    cudaDeviceGetAttribute(&nsm, cudaDevAttrMultiProcessorCount, dev);
    cudaOccupancyMaxActiveBlocksPerMultiprocessor(&occ, k_chain, 256, SMCH);
    if (occ < 1) occ = 1;
    int nb = occ * nsm;
    if (nb > 2 * nsm) nb = 2 * nsm;

    // 10 graph nodes total
    k_init<<<NB_NODE, 256>>>();                                             // 0
    k_edgepre<<<NB_EDGE, 256>>>(ei, ew);                                    // 1
    k_scanLB<<<SCB, 1024>>>();                                              // 2
    k_scatter<<<NB_EDGE, 256>>>(ei, ew);                                    // 3
    k_prep<<<(NX4 + 255) / 256, 256>>>(W_xz, W_xr, W_xh, W_hz, W_hr, W_hh,  // 4
                                       b_xz, b_xr, b_xh, b_hz, b_hr, X, NX4);
    {
        dim3 gs(NB_SPMM, SEQL);
        k_spmmX<<<gs, 256>>>();                                             // 5 (ncu window)
        dim3 gg(NTILE, SEQL);
        k_fgemmX<<<gg, 384, SMX>>>(pbX);                                    // 6
    }
    k_t0<<<(NN * CH + 255) / 256, 256>>>(b_hz, b_hh, out);                  // 7
    k_chain<<<nb, 256, SMCH>>>(out, pbZR, b_hh, nb);                        // 8
    if (out_size >= (int)((SEQL + 1) * SL)) {                               // 9
        int n = (int)SL;
        k_copy<<<(n + 255) / 256, 256>>>(out + (size_t)(SEQL - 1) * SL,
                                         out + (size_t)SEQL * SL, n);
    }
}

// round 15
// speedup vs baseline: 1.1759x; 1.1759x over previous
#include <cuda_runtime.h>
#include <cuda_fp16.h>
#include <math.h>
#include <cstdint>

#define NN 50000
#define NE 800000
#define CH 64
#define SEQL 8
#define KB 192
#define SCB 49
#define PADH 72

static const size_t SL  = (size_t)NN * CH;
static const size_t SLK = (size_t)NN * KB;

// ---------------- static scratch ----------------
__device__ float  g_deg[NN];
__device__ int    g_cnt[NN];
__device__ int    g_off[NN + 1];
__device__ int    g_cur[NN];
__device__ int    g_pref[SCB];
__device__ int    g_rdy[SCB];
__device__ int2   g_cw[NE];                      // packed {col, w-bits}
__device__ __half g_Xh [(size_t)SEQL * NN * CH]; // fp16 X, all t
__device__ __half g_Hh [(size_t)NN * CH];        // fp16 H state
__device__ __half g_HRh[(size_t)NN * CH];        // fp16 H*R
__device__ __half g_T1X[(size_t)NN * CH];        // T1 (X pipeline, stream s1)
__device__ __half g_T1H[(size_t)NN * CH];        // T1 (H chain)
__device__ float  g_GX [(size_t)SEQL * NN * KB]; // x-gate preactivations
__device__ float  g_Z  [(size_t)NN * CH];
__device__ __half g_BX [192 * KB];               // fp16 transposed weights
__device__ __half g_BZR[128 * KB];
__device__ __half g_BH [64 * KB];
__device__ float  g_bX [192];
__device__ float  g_bZR[128];

// ---------------- helpers ----------------
__device__ __forceinline__ void mma_f16(float* d, const uint32_t* a, const uint32_t* b) {
    asm volatile(
        "mma.sync.aligned.m16n8k16.row.col.f32.f16.f16.f32 "
        "{%0,%1,%2,%3}, {%4,%5,%6,%7}, {%8,%9}, {%0,%1,%2,%3};\n"
        : "+f"(d[0]), "+f"(d[1]), "+f"(d[2]), "+f"(d[3])
        : "r"(a[0]), "r"(a[1]), "r"(a[2]), "r"(a[3]), "r"(b[0]), "r"(b[1]));
}

// gather body: 2x software-pipelined, two independent load chains
__device__ __forceinline__ void gather_edges(const uint4* __restrict__ v4,
                                             int s, int e, int sub, int cg,
                                             float* acc) {
    float acc2[8];
#pragma unroll
    for (int k = 0; k < 8; k++) { acc[k] = 0.f; acc2[k] = 0.f; }
    int j = s + sub;
    for (; j + 4 < e; j += 8) {
        int2 ca = g_cw[j], cb = g_cw[j + 4];
        float wa = __int_as_float(ca.y), wb = __int_as_float(cb.y);
        uint4 ua = v4[(size_t)ca.x * 8 + cg];
        uint4 ub = v4[(size_t)cb.x * 8 + cg];
        const __half2* ha = (const __half2*)&ua;
        const __half2* hb = (const __half2*)&ub;
#pragma unroll
        for (int k = 0; k < 4; k++) {
            float2 fa = __half22float2(ha[k]);
            float2 fb = __half22float2(hb[k]);
            acc [2 * k]     += wa * fa.x;
            acc [2 * k + 1] += wa * fa.y;
            acc2[2 * k]     += wb * fb.x;
            acc2[2 * k + 1] += wb * fb.y;
        }
    }
    if (j < e) {
        int2 cw = g_cw[j];
        float w = __int_as_float(cw.y);
        uint4 u = v4[(size_t)cw.x * 8 + cg];
        const __half2* h = (const __half2*)&u;
#pragma unroll
        for (int k = 0; k < 4; k++) {
            float2 f = __half22float2(h[k]);
            acc[2 * k]     += w * f.x;
            acc[2 * k + 1] += w * f.y;
        }
    }
#pragma unroll
    for (int k = 0; k < 8; k++) acc[k] += acc2[k];
#pragma unroll
    for (int d = 8; d <= 16; d <<= 1)
#pragma unroll
        for (int k = 0; k < 8; k++)
            acc[k] += __shfl_xor_sync(0xffffffffu, acc[k], d);
}

// ---------------- setup ----------------
__global__ void k_init() {
    int i = blockIdx.x * blockDim.x + threadIdx.x;
    if (i < NN) { g_deg[i] = 0.f; g_cnt[i] = 0; g_cur[i] = 0; }
    if (i < SCB) g_rdy[i] = 0;
}
__global__ void k_edgepre(const int* __restrict__ ei, const float* __restrict__ ew) {
    int e = blockIdx.x * blockDim.x + threadIdx.x;
    if (e < NE) {
        int r = ei[e], c = ei[NE + e];
        if (r != c) atomicAdd(&g_deg[r], ew[e]);
        atomicAdd(&g_cnt[r], 1);
    }
}
// chained-prefix scan: 49 blocks, block b waits on b-1
__global__ void k_scanLB() {
    __shared__ int sh[1024];
    __shared__ int s_pre;
    int b = blockIdx.x, t = threadIdx.x, idx = b * 1024 + t;
    int v = (idx < NN) ? g_cnt[idx] : 0;
    sh[t] = v; __syncthreads();
    for (int d = 1; d < 1024; d <<= 1) {
        int u = (t >= d) ? sh[t - d] : 0;
        __syncthreads(); sh[t] += u; __syncthreads();
    }
    if (t == 0) {
        int total = sh[1023];
        int pre = 0;
        if (b > 0) {
            while (atomicAdd(&g_rdy[b - 1], 0) == 0) __nanosleep(32);
            __threadfence();
            pre = g_pref[b - 1];
        }
        g_pref[b] = pre + total;
        __threadfence();
        atomicExch(&g_rdy[b], 1);
        s_pre = pre;
    }
    __syncthreads();
    if (idx < NN) g_off[idx] = s_pre + sh[t] - v;
    if (b == SCB - 1 && t == 1023) g_off[NN] = NE;
}
__global__ void k_scatter(const int* __restrict__ ei, const float* __restrict__ ew) {
    int e = blockIdx.x * blockDim.x + threadIdx.x;
    if (e < NE) {
        int r = ei[e], c = ei[NE + e];
        float w = (r == c) ? 0.f : ew[e];
        float dr = g_deg[r], dc = g_deg[c];
        float wn = -w * (dr > 0.f ? rsqrtf(dr) : 0.f) * (dc > 0.f ? rsqrtf(dc) : 0.f);
        int pos = g_off[r] + atomicAdd(&g_cur[r], 1);
        g_cw[pos] = make_int2(c, __float_as_int(wn));
    }
}
// fused: transposed fp16 weights + bias concat + X fp32->fp16
__global__ void k_prep(const float* __restrict__ Wxz, const float* __restrict__ Wxr,
                       const float* __restrict__ Wxh, const float* __restrict__ Whz,
                       const float* __restrict__ Whr, const float* __restrict__ Whh,
                       const float* __restrict__ bxz, const float* __restrict__ bxr,
                       const float* __restrict__ bxh, const float* __restrict__ bhz,
                       const float* __restrict__ bhr, const float* __restrict__ X, int n4) {
    int i = blockIdx.x * blockDim.x + threadIdx.x;
    if (i < 192 * KB) {
        int n = i / KB, k = i % KB, kc = k / 64, ci = k & 63, gate = n / 64, c = n & 63;
        const float* W = gate == 0 ? Wxz : (gate == 1 ? Wxr : Wxh);
        g_BX[i] = __float2half(W[kc * 4096 + ci * 64 + c]);
    }
    if (i < 128 * KB) {
        int n = i / KB, k = i % KB, kc = k / 64, ci = k & 63, c = n & 63;
        const float* W = n < 64 ? Whz : Whr;
        g_BZR[i] = __float2half(W[kc * 4096 + ci * 64 + c]);
    }
    if (i < 64 * KB) {
        int n = i / KB, k = i % KB, kc = k / 64, ci = k & 63;
        g_BH[i] = __float2half(Whh[kc * 4096 + ci * 64 + (n & 63)]);
    }
    if (i < 192) g_bX[i] = i < 64 ? bxz[i] : (i < 128 ? bxr[i - 64] : bxh[i - 128]);
    if (i < 128) g_bZR[i] = i < 64 ? bhz[i] : bhr[i - 64];
    if (i < n4) {
        float4 v = ((const float4*)X)[i];
        __half2 h0 = __floats2half2_rn(v.x, v.y);
        __half2 h1 = __floats2half2_rn(v.z, v.w);
        ((uint2*)g_Xh)[i] = make_uint2(*(uint32_t*)&h0, *(uint32_t*)&h1);
    }
}

// ---------------- SpMM: T1 = S @ vh (quarter-warp per edge, pipelined) ----
__global__ void k_spmmT1(const __half* __restrict__ vh, __half* __restrict__ T1) {
    int warp = (blockIdx.x * blockDim.x + threadIdx.x) >> 5;
    if (warp >= NN) return;
    int lane = threadIdx.x & 31, sub = lane >> 3, cg = lane & 7;
    float acc[8];
    gather_edges((const uint4*)vh, g_off[warp], g_off[warp + 1], sub, cg, acc);
    if (sub == 0) {
        uint4 r; __half2* rh = (__half2*)&r;
#pragma unroll
        for (int k = 0; k < 4; k++) rh[k] = __floats2half2_rn(acc[2 * k], acc[2 * k + 1]);
        ((uint4*)T1)[(size_t)warp * 8 + cg] = r;
    }
}

// ---------------- fused GEMM: T2-gather prologue + fp16 MMA + epilogues ----
// acc = T0@W0 + T1@W1 + T2@W2, T2 = 2*(S@T1) - T0 gathered into smem.
// EPI 0: out[r*KB+c] = acc + bias                                    (GX)
// EPI 1: c<64: Z fp32; c>=64: outh = h(H * sigmoid(acc+bias+GX))
// EPI 2: Ht = tanh(acc+bias+GX[128+]); out = Z*H+(1-Z)*Ht; outh = h(out)
template <int NOUT, int EPI>
__global__ void __launch_bounds__(128 * (NOUT / 64)) k_fgemm(
    const __half* __restrict__ T0, const __half* __restrict__ T1,
    const __half* __restrict__ B, const float* __restrict__ bias,
    const float* __restrict__ GX, const float* __restrict__ H,
    const float* __restrict__ Z, float* __restrict__ out,
    __half* __restrict__ outh, int rows)
{
    extern __shared__ __half sm[];
    __half* As  = sm;                  // 128 * PADH
    __half* T2s = As + 128 * PADH;     // 128 * PADH
    __half* Bs  = T2s + 128 * PADH;    // NOUT * PADH

    const int NTH = 128 * (NOUT / 64);
    const int NW  = NTH / 32;
    int tid = threadIdx.x;
    int wid = tid >> 5, lane = tid & 31;
    int mw = wid & 3, nw = wid >> 2;
    int g = lane >> 2, tq = lane & 3;
    int sub = lane >> 3, cg = lane & 7;
    int rb = blockIdx.x * 128;

    // ---- prologue: gather T2 = 2*(S@T1) - T0 for this block's rows ----
    for (int row = wid; row < 128; row += NW) {
        int gr = rb + row;
        float acc[8];
        if (gr < rows) {
            gather_edges((const uint4*)T1, g_off[gr], g_off[gr + 1], sub, cg, acc);
        } else {
#pragma unroll
            for (int k = 0; k < 8; k++) acc[k] = 0.f;
        }
        if (sub == 0) {
            uint4 t0u = make_uint4(0u, 0u, 0u, 0u);
            if (gr < rows) t0u = *(const uint4*)(T0 + (size_t)gr * CH + cg * 8);
            const __half2* th = (const __half2*)&t0u;
            uint4 r; __half2* rh = (__half2*)&r;
#pragma unroll
            for (int k = 0; k < 4; k++) {
                float2 tf = __half22float2(th[k]);
                rh[k] = __floats2half2_rn(2.f * acc[2 * k] - tf.x,
                                          2.f * acc[2 * k + 1] - tf.y);
            }
            *(uint4*)&T2s[row * PADH + cg * 8] = r;
        }
    }
    __syncthreads();

    // ---- main loop: 3 k-chunks of 64 halves ----
    float acc[2][8][4];
#pragma unroll
    for (int mt = 0; mt < 2; mt++)
#pragma unroll
        for (int nt = 0; nt < 8; nt++)
#pragma unroll
            for (int q = 0; q < 4; q++) acc[mt][nt][q] = 0.f;

    for (int kc = 0; kc < 3; kc++) {
        if (kc < 2) {
            const __half* Asrc = (kc == 0) ? T0 : T1;
#pragma unroll
            for (int idx = tid; idx < 1024; idx += NTH) {
                int row = idx >> 3, q = idx & 7;
                uint4 v = make_uint4(0u, 0u, 0u, 0u);
                int gr = rb + row;
                if (gr < rows) v = *(const uint4*)(Asrc + (size_t)gr * CH + q * 8);
                *(uint4*)&As[row * PADH + q * 8] = v;
            }
        }
#pragma unroll
        for (int idx = tid; idx < NOUT * 8; idx += NTH) {
            int row = idx >> 3, q = idx & 7;
            uint4 v = *(const uint4*)(B + (size_t)row * KB + kc * 64 + q * 8);
            *(uint4*)&Bs[row * PADH + q * 8] = v;
        }
        __syncthreads();
        const __half* At = (kc == 2) ? T2s : As;
#pragma unroll
        for (int kk = 0; kk < 4; kk++) {
            int kb = kk * 16 + tq * 2;
            uint32_t a[2][4];
#pragma unroll
            for (int mt = 0; mt < 2; mt++) {
                int r = mw * 32 + mt * 16 + g;
                a[mt][0] = *(const uint32_t*)&At[r * PADH + kb];
                a[mt][1] = *(const uint32_t*)&At[(r + 8) * PADH + kb];
                a[mt][2] = *(const uint32_t*)&At[r * PADH + kb + 8];
                a[mt][3] = *(const uint32_t*)&At[(r + 8) * PADH + kb + 8];
            }
            uint32_t b[8][2];
#pragma unroll
            for (int nt = 0; nt < 8; nt++) {
                int n = nw * 64 + nt * 8 + g;
                b[nt][0] = *(const uint32_t*)&Bs[n * PADH + kb];
                b[nt][1] = *(const uint32_t*)&Bs[n * PADH + kb + 8];
            }
#pragma unroll
            for (int mt = 0; mt < 2; mt++)
#pragma unroll
                for (int nt = 0; nt < 8; nt++)
                    mma_f16(acc[mt][nt], a[mt], b[nt]);
        }
        __syncthreads();
    }

    // ---- epilogue ----
#pragma unroll
    for (int mt = 0; mt < 2; mt++) {
#pragma unroll
        for (int nt = 0; nt < 8; nt++) {
            int c = nw * 64 + nt * 8 + tq * 2;
            float bx = bias[c], by = bias[c + 1];
#pragma unroll
            for (int hh = 0; hh < 2; hh++) {
                int r = rb + mw * 32 + mt * 16 + g + hh * 8;
                if (r >= rows) continue;
                float vx = acc[mt][nt][hh * 2] + bx;
                float vy = acc[mt][nt][hh * 2 + 1] + by;
                if (EPI == 0) {
                    *(float2*)(out + (size_t)r * KB + c) = make_float2(vx, vy);
                } else if (EPI == 1) {
                    float2 gx = *(const float2*)(GX + (size_t)r * KB + c);
                    float sx = 1.f / (1.f + expf(-(vx + gx.x)));
                    float sy = 1.f / (1.f + expf(-(vy + gx.y)));
                    if (c < 64) {
                        *(float2*)(out + (size_t)r * CH + c) = make_float2(sx, sy);
                    } else {
                        float2 h = *(const float2*)(H + (size_t)r * CH + (c - 64));
                        *(__half2*)(outh + (size_t)r * CH + (c - 64)) =
                            __floats2half2_rn(h.x * sx, h.y * sy);
                    }
                } else {
                    float2 gx = *(const float2*)(GX + (size_t)r * KB + 128 + c);
                    float2 h  = *(const float2*)(H + (size_t)r * CH + c);
                    float2 z2 = *(const float2*)(Z + (size_t)r * CH + c);
                    float tx = tanhf(vx + gx.x), ty = tanhf(vy + gx.y);
                    float ox = z2.x * h.x + (1.f - z2.x) * tx;
                    float oy = z2.y * h.y + (1.f - z2.y) * ty;
                    *(float2*)(out + (size_t)r * CH + c) = make_float2(ox, oy);
                    *(__half2*)(outh + (size_t)r * CH + c) = __floats2half2_rn(ox, oy);
                }
            }
        }
    }
}

// t = 0: H0 = 0 => Hn = (1 - sigmoid(GXz + b_hz)) * tanh(GXh + b_hh)
__global__ void k_t0(const float* __restrict__ bhz, const float* __restrict__ bhh,
                     float* __restrict__ out) {
    int i = blockIdx.x * blockDim.x + threadIdx.x;
    if (i >= NN * CH) return;
    int r = i >> 6, c = i & 63;
    float z  = 1.f / (1.f + expf(-(g_GX[(size_t)r * KB + c] + bhz[c])));
    float ht = tanhf(g_GX[(size_t)r * KB + 128 + c] + bhh[c]);
    float res = (1.f - z) * ht;
    out[i] = res;
    g_Hh[i] = __float2half(res);
}

__global__ void k_copy(const float* __restrict__ src, float* __restrict__ dst, int n) {
    int i = blockIdx.x * blockDim.x + threadIdx.x;
    if (i < n) dst[i] = src[i];
}

// ---------------- host side ----------------
extern "C" void kernel_launch(void* const* d_in, const int* in_sizes, int n_in,
                              void* d_out, int out_size) {
    const float* X    = (const float*)d_in[0];
    const int*   ei   = (const int*)  d_in[1];
    const float* ew   = (const float*)d_in[2];
    const float* W_xz = (const float*)d_in[3];
    const float* b_xz = (const float*)d_in[4];
    const float* W_hz = (const float*)d_in[5];
    const float* b_hz = (const float*)d_in[6];
    const float* W_xr = (const float*)d_in[7];
    const float* b_xr = (const float*)d_in[8];
    const float* W_hr = (const float*)d_in[9];
    const float* b_hr = (const float*)d_in[10];
    const float* W_xh = (const float*)d_in[11];
    const float* b_xh = (const float*)d_in[12];
    const float* W_hh = (const float*)d_in[13];
    const float* b_hh = (const float*)d_in[14];
    float* out = (float*)d_out;

    __half *pXh, *pHh, *pHRh, *pT1X, *pT1H, *pBX, *pBZR, *pBH;
    float  *pGX, *pZ, *pbX, *pbZR;
    cudaGetSymbolAddress((void**)&pXh,  g_Xh);
    cudaGetSymbolAddress((void**)&pHh,  g_Hh);
    cudaGetSymbolAddress((void**)&pHRh, g_HRh);
    cudaGetSymbolAddress((void**)&pT1X, g_T1X);
    cudaGetSymbolAddress((void**)&pT1H, g_T1H);
    cudaGetSymbolAddress((void**)&pGX,  g_GX);
    cudaGetSymbolAddress((void**)&pZ,   g_Z);
    cudaGetSymbolAddress((void**)&pBX,  g_BX);
    cudaGetSymbolAddress((void**)&pBZR, g_BZR);
    cudaGetSymbolAddress((void**)&pBH,  g_BH);
    cudaGetSymbolAddress((void**)&pbX,  g_bX);
    cudaGetSymbolAddress((void**)&pbZR, g_bZR);

    const int NB_NODE = (NN + 255) / 256;
    const int NB_EDGE = (NE + 255) / 256;
    const int NB_SPMM = (NN * 32 + 255) / 256;
    const int NB_GEMM = (NN + 127) / 128;
    const int NX4 = SEQL * NN * CH / 4;
    const int SM192 = (128 * 2 + 192) * PADH * (int)sizeof(__half);
    const int SM128 = (128 * 2 + 128) * PADH * (int)sizeof(__half);
    const int SM64  = (128 * 2 + 64)  * PADH * (int)sizeof(__half);

    cudaFuncSetAttribute(k_fgemm<192, 0>, cudaFuncAttributeMaxDynamicSharedMemorySize, SM192);
    cudaFuncSetAttribute(k_fgemm<128, 1>, cudaFuncAttributeMaxDynamicSharedMemorySize, SM128);
    cudaFuncSetAttribute(k_fgemm<64, 2>,  cudaFuncAttributeMaxDynamicSharedMemorySize, SM64);

    // setup (5 nodes)
    k_init<<<NB_NODE, 256>>>();
    k_edgepre<<<NB_EDGE, 256>>>(ei, ew);
    k_scanLB<<<SCB, 1024>>>();
    k_scatter<<<NB_EDGE, 256>>>(ei, ew);
    k_prep<<<(NX4 + 255) / 256, 256>>>(W_xz, W_xr, W_xh, W_hz, W_hr, W_hh,
                                       b_xz, b_xr, b_xh, b_hz, b_hr, X, NX4);

    // fork side stream for the per-t X pipeline
    cudaStream_t s1;
    cudaStreamCreateWithFlags(&s1, cudaStreamNonBlocking);
    cudaEvent_t evSetup, evX[SEQL];
    cudaEventCreateWithFlags(&evSetup, cudaEventDisableTiming);
    for (int t = 0; t < SEQL; t++)
        cudaEventCreateWithFlags(&evX[t], cudaEventDisableTiming);

    cudaEventRecord(evSetup, 0);
    cudaStreamWaitEvent(s1, evSetup, 0);
    for (int t = 0; t < SEQL; t++) {
        const __half* Xt = pXh + (size_t)t * SL;
        k_spmmT1<<<NB_SPMM, 256, 0, s1>>>(Xt, pT1X);
        k_fgemm<192, 0><<<NB_GEMM, 384, SM192, s1>>>(
            Xt, pT1X, pBX, pbX, nullptr, nullptr, nullptr,
            pGX + (size_t)t * SLK, nullptr, NN);
        cudaEventRecord(evX[t], s1);
    }

    // main-stream H chain
    cudaStreamWaitEvent(0, evX[0], 0);
    k_t0<<<(NN * CH + 255) / 256, 256>>>(b_hz, b_hh, out);

    for (int t = 1; t < SEQL; t++) {
        const float* Hp  = out + (size_t)(t - 1) * SL;
        const float* GXt = pGX + (size_t)t * SLK;
        float* Ot = out + (size_t)t * SL;

        k_spmmT1<<<NB_SPMM, 256>>>(pHh, pT1H);
        cudaStreamWaitEvent(0, evX[t], 0);
        k_fgemm<128, 1><<<NB_GEMM, 256, SM128>>>(
            pHh, pT1H, pBZR, pbZR, GXt, Hp, nullptr, pZ, pHRh, NN);
        k_spmmT1<<<NB_SPMM, 256>>>(pHRh, pT1H);
        k_fgemm<64, 2><<<NB_GEMM, 128, SM64>>>(
            pHRh, pT1H, pBH, b_hh, GXt, Hp, pZ, Ot, pHh, NN);
    }

    // Hlast = States[:, -1]
    if (out_size >= (int)((SEQL + 1) * SL)) {
        int n = (int)SL;
        k_copy<<<(n + 255) / 256, 256>>>(out + (size_t)(SEQL - 1) * SL,
                                         out + (size_t)SEQL * SL, n);
    }
}